// round 7
// baseline (speedup 1.0000x reference)
#include <cuda_runtime.h>
#include <cuda_bf16.h>
#include <cstdint>

// out[g] = x[g] @ Q[g], Q = H_0..H_127 (Householder composition).
// Kernel A: build Q rows in parallel, emit Q^T (k-major) as bf16 hi/lo.
// Kernel B: mma.sync bf16 GEMM, 3-product hi/lo split. MT=64, 128 thr,
//           2m x 2n warps (32m x 64n per warp -> 1.0 smem-wf per MMA),
//           2 CTAs/SM for stage/MMA overlap.

#define G 16
#define MROWS 16384
#define C 128
#define MT 64          // m-tile per CTA
#define SP 136         // padded smem row stride in bf16 elements

__device__ __nv_bfloat16 Qt_hi[G * C * C];  // [g][n][k], k contiguous
__device__ __nv_bfloat16 Qt_lo[G * C * C];

__device__ __forceinline__ uint32_t smem_u32(const void* p) {
    uint32_t a;
    asm("{ .reg .u64 t; cvta.to.shared.u64 t, %1; cvt.u32.u64 %0, t; }"
        : "=r"(a) : "l"(p));
    return a;
}

__device__ __forceinline__ void cp_async16(uint32_t saddr, const void* gaddr) {
    asm volatile("cp.async.cg.shared.global [%0], [%1], 16;"
                 :: "r"(saddr), "l"(gaddr) : "memory");
}
__device__ __forceinline__ void cp_async_commit_wait() {
    asm volatile("cp.async.commit_group;" ::: "memory");
    asm volatile("cp.async.wait_group 0;" ::: "memory");
}

__device__ __forceinline__ void ldmatrix_x4(uint32_t& r0, uint32_t& r1,
                                            uint32_t& r2, uint32_t& r3,
                                            uint32_t addr) {
    asm volatile("ldmatrix.sync.aligned.m8n8.x4.shared.b16 {%0,%1,%2,%3}, [%4];"
                 : "=r"(r0), "=r"(r1), "=r"(r2), "=r"(r3) : "r"(addr));
}

__device__ __forceinline__ void mma_bf16(float* d, const uint32_t* a,
                                         uint32_t b0, uint32_t b1) {
    asm volatile(
        "mma.sync.aligned.m16n8k16.row.col.f32.bf16.bf16.f32 "
        "{%0,%1,%2,%3}, {%4,%5,%6,%7}, {%8,%9}, {%0,%1,%2,%3};"
        : "+f"(d[0]), "+f"(d[1]), "+f"(d[2]), "+f"(d[3])
        : "r"(a[0]), "r"(a[1]), "r"(a[2]), "r"(a[3]), "r"(b0), "r"(b1));
}

// ==================== Kernel A: build Q (transposed, bf16 hi/lo) ====================
__global__ void __launch_bounds__(128) buildq_kernel(const float* __restrict__ W) {
    extern __shared__ float sm[];
    float* WshT = sm;              // [128][129]
    float* rden = sm + 128 * 129;  // [128]

    const int g  = blockIdx.x >> 3;
    const int rb = blockIdx.x & 7;
    const float* Wg = W + (size_t)g * C * C;
    const int t = threadIdx.x;

    #pragma unroll 8
    for (int k = 0; k < C; k++) WshT[t * 129 + k] = Wg[k * C + t];
    __syncthreads();

    {
        const float* row = &WshT[t * 129];
        float s = 0.0f;
        #pragma unroll 8
        for (int k = 0; k < C; k++) s = fmaf(row[k], row[k], s);
        rden[t] = 2.0f / s;
    }
    __syncthreads();

    const int r = t >> 3;
    const int p = t & 7;
    const int R = rb * 16 + r;  // row of Q (= K index of Q^T)

    float M[16];
    #pragma unroll
    for (int j = 0; j < 16; j++) M[j] = (R == (p + 8 * j)) ? 1.0f : 0.0f;

    for (int i = 0; i < C; i++) {
        const float* wrow = &WshT[i * 129 + p];
        float wv[16];
        float d0 = 0.0f, d1 = 0.0f;
        #pragma unroll
        for (int j = 0; j < 16; j++) {
            wv[j] = wrow[8 * j];
            if (j & 1) d1 = fmaf(M[j], wv[j], d1);
            else       d0 = fmaf(M[j], wv[j], d0);
        }
        float d = d0 + d1;
        d += __shfl_xor_sync(0xffffffffu, d, 1, 8);
        d += __shfl_xor_sync(0xffffffffu, d, 2, 8);
        d += __shfl_xor_sync(0xffffffffu, d, 4, 8);
        const float c = d * rden[i];
        #pragma unroll
        for (int j = 0; j < 16; j++) M[j] = fmaf(-c, wv[j], M[j]);
    }

    #pragma unroll
    for (int j = 0; j < 16; j++) {
        const int n = p + 8 * j;
        const size_t idx = ((size_t)g * C + n) * C + R;
        __nv_bfloat16 hi = __float2bfloat16_rn(M[j]);
        __nv_bfloat16 lo = __float2bfloat16_rn(M[j] - __bfloat162float(hi));
        Qt_hi[idx] = hi;
        Qt_lo[idx] = lo;
    }
}

// ==================== Kernel B: mma.sync GEMM, 2m x 2n warps ====================
#define AH_OFF 0
#define AL_OFF (MT * SP * 2)
#define BH_OFF (2 * MT * SP * 2)
#define BL_OFF (2 * MT * SP * 2 + C * SP * 2)
#define SMEM_MMA (2 * MT * SP * 2 + 2 * C * SP * 2)   // 104448 bytes

__global__ void __launch_bounds__(128, 2) mma_kernel(const float* __restrict__ X,
                                                     float* __restrict__ Out) {
    extern __shared__ char smem[];
    const uint32_t sb = smem_u32(smem);
    const int t  = threadIdx.x;
    const int w  = t >> 5;
    const int l  = t & 31;
    const int wm = w & 1;    // m-warp: rows [32*wm, 32*wm+32)
    const int wn = w >> 1;   // n-warp: cols [64*wn, 64*wn+64)
    const int m0 = blockIdx.x * MT;
    const int g  = blockIdx.y;

    // ---- stage Q^T hi/lo via cp.async (raw bf16 copy) ----
    const char* qh = (const char*)(Qt_hi + (size_t)g * C * C);
    const char* ql = (const char*)(Qt_lo + (size_t)g * C * C);
    #pragma unroll
    for (int it = 0; it < 16; it++) {
        const int idx = t + 128 * it;          // 2048 uint4 chunks (8 bf16)
        const int row = idx >> 4;
        const int c8  = (idx & 15) * 8;
        const uint32_t off = (uint32_t)(row * SP + c8) * 2;
        cp_async16(sb + BH_OFF + off, qh + idx * 16);
        cp_async16(sb + BL_OFF + off, ql + idx * 16);
    }

    // ---- stage x tile (64 x 128 fp32) -> bf16 hi/lo ----
    const float4* xg = (const float4*)(X + ((size_t)g * MROWS + m0) * C);
    #pragma unroll
    for (int it = 0; it < 16; it++) {
        const int idx = t + 128 * it;          // 2048 float4
        const int row = idx >> 5;
        const int c4  = (idx & 31) * 4;
        const float4 v = xg[idx];
        const float vv[4] = {v.x, v.y, v.z, v.w};
        __nv_bfloat16 h[4], e[4];
        #pragma unroll
        for (int i = 0; i < 4; i++) {
            h[i] = __float2bfloat16_rn(vv[i]);
            e[i] = __float2bfloat16_rn(vv[i] - __bfloat162float(h[i]));
        }
        const uint32_t off = (uint32_t)(row * SP + c4) * 2;
        *(uint2*)(smem + AH_OFF + off) = *(const uint2*)h;
        *(uint2*)(smem + AL_OFF + off) = *(const uint2*)e;
    }

    cp_async_commit_wait();
    __syncthreads();

    // ---- mainloop: per warp 32m x 64n ----
    float acc[2][8][4];
    #pragma unroll
    for (int mt = 0; mt < 2; mt++)
        #pragma unroll
        for (int nt = 0; nt < 8; nt++)
            #pragma unroll
            for (int i = 0; i < 4; i++) acc[mt][nt][i] = 0.0f;

    const int a_row  = (l & 7) + 8 * ((l >> 3) & 1);
    const int a_col8 = 8 * (l >> 4);
    const int b_row_in = (l & 7) + 8 * (l >> 4);
    const int b_col8   = 8 * ((l >> 3) & 1);

    const uint32_t aoff0 = (uint32_t)((32 * wm + a_row) * SP + a_col8) * 2;
    const uint32_t aoff1 = (uint32_t)((32 * wm + 16 + a_row) * SP + a_col8) * 2;

    #pragma unroll
    for (int ks = 0; ks < 8; ks++) {
        const int k0 = 16 * ks;
        uint32_t ah0[4], al0[4], ah1[4], al1[4];
        ldmatrix_x4(ah0[0], ah0[1], ah0[2], ah0[3], sb + AH_OFF + aoff0 + k0 * 2);
        ldmatrix_x4(al0[0], al0[1], al0[2], al0[3], sb + AL_OFF + aoff0 + k0 * 2);
        ldmatrix_x4(ah1[0], ah1[1], ah1[2], ah1[3], sb + AH_OFF + aoff1 + k0 * 2);
        ldmatrix_x4(al1[0], al1[1], al1[2], al1[3], sb + AL_OFF + aoff1 + k0 * 2);

        #pragma unroll
        for (int jj = 0; jj < 4; jj++) {
            const uint32_t boff =
                (uint32_t)((64 * wn + 16 * jj + b_row_in) * SP + k0 + b_col8) * 2;
            uint32_t bh0, bh1, bh2, bh3, bl0, bl1, bl2, bl3;
            ldmatrix_x4(bh0, bh1, bh2, bh3, sb + BH_OFF + boff);
            ldmatrix_x4(bl0, bl1, bl2, bl3, sb + BL_OFF + boff);

            // m-tile 0
            mma_bf16(acc[0][2 * jj],     ah0, bh0, bh1);
            mma_bf16(acc[0][2 * jj],     ah0, bl0, bl1);
            mma_bf16(acc[0][2 * jj],     al0, bh0, bh1);
            mma_bf16(acc[0][2 * jj + 1], ah0, bh2, bh3);
            mma_bf16(acc[0][2 * jj + 1], ah0, bl2, bl3);
            mma_bf16(acc[0][2 * jj + 1], al0, bh2, bh3);
            // m-tile 1
            mma_bf16(acc[1][2 * jj],     ah1, bh0, bh1);
            mma_bf16(acc[1][2 * jj],     ah1, bl0, bl1);
            mma_bf16(acc[1][2 * jj],     al1, bh0, bh1);
            mma_bf16(acc[1][2 * jj + 1], ah1, bh2, bh3);
            mma_bf16(acc[1][2 * jj + 1], ah1, bl2, bl3);
            mma_bf16(acc[1][2 * jj + 1], al1, bh2, bh3);
        }
    }

    // ---- epilogue ----
    const int rr = l >> 2;
    const int cn = 64 * wn + 2 * (l & 3);
    #pragma unroll
    for (int mt = 0; mt < 2; mt++) {
        const int r0 = 32 * wm + 16 * mt + rr;
        float* ob = Out + ((size_t)g * MROWS + m0 + r0) * C + cn;
        #pragma unroll
        for (int nt = 0; nt < 8; nt++) {
            *(float2*)(ob + 8 * nt)         = make_float2(acc[mt][nt][0], acc[mt][nt][1]);
            *(float2*)(ob + 8 * C + 8 * nt) = make_float2(acc[mt][nt][2], acc[mt][nt][3]);
        }
    }
}

// ==================== launch ====================
extern "C" void kernel_launch(void* const* d_in, const int* in_sizes, int n_in,
                              void* d_out, int out_size) {
    const float* x = (const float*)d_in[0];
    const float* w = (const float*)d_in[1];
    if (n_in >= 2 && in_sizes[0] < in_sizes[1]) {
        const float* tmp = x; x = w; w = tmp;
    }
    float* out = (float*)d_out;

    const int smemA = 128 * 129 * 4 + 128 * 4;  // 66560
    cudaFuncSetAttribute((const void*)buildq_kernel,
                         cudaFuncAttributeMaxDynamicSharedMemorySize, smemA);
    cudaFuncSetAttribute((const void*)mma_kernel,
                         cudaFuncAttributeMaxDynamicSharedMemorySize, SMEM_MMA);

    buildq_kernel<<<G * 8, 128, smemA>>>(w);
    mma_kernel<<<dim3(MROWS / MT, G), 128, SMEM_MMA>>>(x, out);
}

// round 8
// speedup vs baseline: 1.0764x; 1.0764x over previous
#include <cuda_runtime.h>
#include <cuda_bf16.h>
#include <cstdint>

// out[g] = x[g] @ Q[g], Q = H_0..H_127 (Householder composition).
// Kernel A: build Q rows in parallel, emit Q^T (k-major) as bf16 hi/lo.
// Kernel B: mma.sync bf16 GEMM, 3-product hi/lo split. Persistent-ish CTA:
//           4 m-tiles per CTA, B loaded once, x prefetched (cp.async double
//           buffer) so DRAM streams under the tensor mainloop.

#define G 16
#define MROWS 16384
#define C 128
#define MT 64          // rows per m-tile
#define TPC 4          // m-tiles per CTA
#define SP 136         // padded smem row stride in bf16 elements

__device__ __nv_bfloat16 Qt_hi[G * C * C];  // [g][n][k], k contiguous
__device__ __nv_bfloat16 Qt_lo[G * C * C];

__device__ __forceinline__ uint32_t smem_u32(const void* p) {
    uint32_t a;
    asm("{ .reg .u64 t; cvta.to.shared.u64 t, %1; cvt.u32.u64 %0, t; }"
        : "=r"(a) : "l"(p));
    return a;
}

__device__ __forceinline__ void cp_async16(uint32_t saddr, const void* gaddr) {
    asm volatile("cp.async.cg.shared.global [%0], [%1], 16;"
                 :: "r"(saddr), "l"(gaddr) : "memory");
}
__device__ __forceinline__ void cp_async_commit() {
    asm volatile("cp.async.commit_group;" ::: "memory");
}
template <int N>
__device__ __forceinline__ void cp_async_wait() {
    asm volatile("cp.async.wait_group %0;" :: "n"(N) : "memory");
}

__device__ __forceinline__ void ldmatrix_x4(uint32_t& r0, uint32_t& r1,
                                            uint32_t& r2, uint32_t& r3,
                                            uint32_t addr) {
    asm volatile("ldmatrix.sync.aligned.m8n8.x4.shared.b16 {%0,%1,%2,%3}, [%4];"
                 : "=r"(r0), "=r"(r1), "=r"(r2), "=r"(r3) : "r"(addr));
}

__device__ __forceinline__ void mma_bf16(float* d, const uint32_t* a,
                                         uint32_t b0, uint32_t b1) {
    asm volatile(
        "mma.sync.aligned.m16n8k16.row.col.f32.bf16.bf16.f32 "
        "{%0,%1,%2,%3}, {%4,%5,%6,%7}, {%8,%9}, {%0,%1,%2,%3};"
        : "+f"(d[0]), "+f"(d[1]), "+f"(d[2]), "+f"(d[3])
        : "r"(a[0]), "r"(a[1]), "r"(a[2]), "r"(a[3]), "r"(b0), "r"(b1));
}

// ==================== Kernel A: build Q (transposed, bf16 hi/lo) ====================
__global__ void __launch_bounds__(128) buildq_kernel(const float* __restrict__ W) {
    extern __shared__ float sm[];
    float* WshT = sm;              // [128][129]
    float* rden = sm + 128 * 129;  // [128]

    const int g  = blockIdx.x >> 3;
    const int rb = blockIdx.x & 7;
    const float* Wg = W + (size_t)g * C * C;
    const int t = threadIdx.x;

    #pragma unroll 8
    for (int k = 0; k < C; k++) WshT[t * 129 + k] = Wg[k * C + t];
    __syncthreads();

    {
        const float* row = &WshT[t * 129];
        float s = 0.0f;
        #pragma unroll 8
        for (int k = 0; k < C; k++) s = fmaf(row[k], row[k], s);
        rden[t] = 2.0f / s;
    }
    __syncthreads();

    const int r = t >> 3;
    const int p = t & 7;
    const int R = rb * 16 + r;

    float M[16];
    #pragma unroll
    for (int j = 0; j < 16; j++) M[j] = (R == (p + 8 * j)) ? 1.0f : 0.0f;

    for (int i = 0; i < C; i++) {
        const float* wrow = &WshT[i * 129 + p];
        float wv[16];
        float d0 = 0.0f, d1 = 0.0f;
        #pragma unroll
        for (int j = 0; j < 16; j++) {
            wv[j] = wrow[8 * j];
            if (j & 1) d1 = fmaf(M[j], wv[j], d1);
            else       d0 = fmaf(M[j], wv[j], d0);
        }
        float d = d0 + d1;
        d += __shfl_xor_sync(0xffffffffu, d, 1, 8);
        d += __shfl_xor_sync(0xffffffffu, d, 2, 8);
        d += __shfl_xor_sync(0xffffffffu, d, 4, 8);
        const float c = d * rden[i];
        #pragma unroll
        for (int j = 0; j < 16; j++) M[j] = fmaf(-c, wv[j], M[j]);
    }

    #pragma unroll
    for (int j = 0; j < 16; j++) {
        const int n = p + 8 * j;
        const size_t idx = ((size_t)g * C + n) * C + R;
        __nv_bfloat16 hi = __float2bfloat16_rn(M[j]);
        __nv_bfloat16 lo = __float2bfloat16_rn(M[j] - __bfloat162float(hi));
        Qt_hi[idx] = hi;
        Qt_lo[idx] = lo;
    }
}

// ==================== Kernel B layout ====================
#define BH_OFF 0
#define BL_OFF (C * SP * 2)
#define AH_OFF (2 * C * SP * 2)
#define AL_OFF (2 * C * SP * 2 + MT * SP * 2)
#define XF_OFF (2 * C * SP * 2 + 2 * MT * SP * 2)
#define XF_BYTES (MT * C * 4)
#define SMEM_MMA (XF_OFF + 2 * XF_BYTES)   // 169984 bytes

__global__ void __launch_bounds__(256, 1) mma_kernel(const float* __restrict__ X,
                                                     float* __restrict__ Out) {
    extern __shared__ char smem[];
    const uint32_t sb = smem_u32(smem);
    const int t  = threadIdx.x;
    const int w  = t >> 5;
    const int l  = t & 31;
    const int wm = w & 1;    // m-warp: rows [32*wm, 32*wm+32)
    const int wn = w >> 1;   // n-warp: cols [32*wn, 32*wn+32)
    const int g  = blockIdx.y;
    const size_t gm_base = (size_t)g * MROWS + (size_t)blockIdx.x * (MT * TPC);

    // ---- prologue: B (once) + x tile 0, one cp.async group ----
    const char* qh = (const char*)(Qt_hi + (size_t)g * C * C);
    const char* ql = (const char*)(Qt_lo + (size_t)g * C * C);
    #pragma unroll
    for (int it = 0; it < 8; it++) {
        const int idx = t + 256 * it;          // 2048 uint4 chunks per B tensor
        const int row = idx >> 4;
        const int c8  = (idx & 15) * 8;
        const uint32_t off = (uint32_t)(row * SP + c8) * 2;
        cp_async16(sb + BH_OFF + off, qh + idx * 16);
        cp_async16(sb + BL_OFF + off, ql + idx * 16);
    }
    {
        const char* xg = (const char*)(X + gm_base * C);
        #pragma unroll
        for (int it = 0; it < 8; it++) {
            const int idx = t + 256 * it;      // 2048 float4
            cp_async16(sb + XF_OFF + idx * 16, xg + idx * 16);
        }
    }
    cp_async_commit();

    // ldmatrix lane address components
    const int a_row  = (l & 7) + 8 * ((l >> 3) & 1);
    const int a_col8 = 8 * (l >> 4);
    const int b_row_in = (l & 7) + 8 * (l >> 4);
    const int b_col8   = 8 * ((l >> 3) & 1);
    const uint32_t aoff0 = (uint32_t)((32 * wm + a_row) * SP + a_col8) * 2;
    const uint32_t aoff1 = (uint32_t)((32 * wm + 16 + a_row) * SP + a_col8) * 2;

    for (int tile = 0; tile < TPC; tile++) {
        const int buf = tile & 1;

        // prefetch next tile's x into the other buffer
        if (tile < TPC - 1) {
            const char* xg = (const char*)(X + (gm_base + (size_t)(tile + 1) * MT) * C);
            const uint32_t xdst = sb + XF_OFF + (buf ^ 1) * XF_BYTES;
            #pragma unroll
            for (int it = 0; it < 8; it++) {
                const int idx = t + 256 * it;
                cp_async16(xdst + idx * 16, xg + idx * 16);
            }
            cp_async_commit();
            cp_async_wait<1>();   // current tile's data (and B) resident
        } else {
            cp_async_wait<0>();
        }
        __syncthreads();

        // ---- convert XF[buf] (fp32) -> AH/AL (bf16 hi/lo) ----
        {
            const float4* xf = (const float4*)(smem + XF_OFF + buf * XF_BYTES);
            #pragma unroll
            for (int it = 0; it < 8; it++) {
                const int idx = t + 256 * it;       // 2048 float4
                const int row = idx >> 5;
                const int c4  = (idx & 31) * 4;
                const float4 v = xf[idx];
                const float vv[4] = {v.x, v.y, v.z, v.w};
                __nv_bfloat16 h[4], e[4];
                #pragma unroll
                for (int i = 0; i < 4; i++) {
                    h[i] = __float2bfloat16_rn(vv[i]);
                    e[i] = __float2bfloat16_rn(vv[i] - __bfloat162float(h[i]));
                }
                const uint32_t off = (uint32_t)(row * SP + c4) * 2;
                *(uint2*)(smem + AH_OFF + off) = *(const uint2*)h;
                *(uint2*)(smem + AL_OFF + off) = *(const uint2*)e;
            }
        }
        __syncthreads();

        // ---- mainloop: per warp 32m x 32n ----
        float acc[2][4][4];
        #pragma unroll
        for (int mt = 0; mt < 2; mt++)
            #pragma unroll
            for (int nt = 0; nt < 4; nt++)
                #pragma unroll
                for (int i = 0; i < 4; i++) acc[mt][nt][i] = 0.0f;

        #pragma unroll
        for (int ks = 0; ks < 8; ks++) {
            const int k0 = 16 * ks;
            uint32_t ah0[4], al0[4], ah1[4], al1[4];
            ldmatrix_x4(ah0[0], ah0[1], ah0[2], ah0[3], sb + AH_OFF + aoff0 + k0 * 2);
            ldmatrix_x4(al0[0], al0[1], al0[2], al0[3], sb + AL_OFF + aoff0 + k0 * 2);
            ldmatrix_x4(ah1[0], ah1[1], ah1[2], ah1[3], sb + AH_OFF + aoff1 + k0 * 2);
            ldmatrix_x4(al1[0], al1[1], al1[2], al1[3], sb + AL_OFF + aoff1 + k0 * 2);

            #pragma unroll
            for (int jj = 0; jj < 2; jj++) {
                const uint32_t boff =
                    (uint32_t)((32 * wn + 16 * jj + b_row_in) * SP + k0 + b_col8) * 2;
                uint32_t bh0, bh1, bh2, bh3, bl0, bl1, bl2, bl3;
                ldmatrix_x4(bh0, bh1, bh2, bh3, sb + BH_OFF + boff);
                ldmatrix_x4(bl0, bl1, bl2, bl3, sb + BL_OFF + boff);

                // m-tile 0
                mma_bf16(acc[0][2 * jj],     ah0, bh0, bh1);
                mma_bf16(acc[0][2 * jj],     ah0, bl0, bl1);
                mma_bf16(acc[0][2 * jj],     al0, bh0, bh1);
                mma_bf16(acc[0][2 * jj + 1], ah0, bh2, bh3);
                mma_bf16(acc[0][2 * jj + 1], ah0, bl2, bl3);
                mma_bf16(acc[0][2 * jj + 1], al0, bh2, bh3);
                // m-tile 1
                mma_bf16(acc[1][2 * jj],     ah1, bh0, bh1);
                mma_bf16(acc[1][2 * jj],     ah1, bl0, bl1);
                mma_bf16(acc[1][2 * jj],     al1, bh0, bh1);
                mma_bf16(acc[1][2 * jj + 1], ah1, bh2, bh3);
                mma_bf16(acc[1][2 * jj + 1], ah1, bl2, bl3);
                mma_bf16(acc[1][2 * jj + 1], al1, bh2, bh3);
            }
        }

        // ---- epilogue ----
        const int rr = l >> 2;
        const int cn = 32 * wn + 2 * (l & 3);
        #pragma unroll
        for (int mt = 0; mt < 2; mt++) {
            const int r0 = 32 * wm + 16 * mt + rr;
            float* ob = Out + (gm_base + (size_t)tile * MT + r0) * C + cn;
            #pragma unroll
            for (int nt = 0; nt < 4; nt++) {
                *(float2*)(ob + 8 * nt)         = make_float2(acc[mt][nt][0], acc[mt][nt][1]);
                *(float2*)(ob + 8 * C + 8 * nt) = make_float2(acc[mt][nt][2], acc[mt][nt][3]);
            }
        }
        __syncthreads();   // protect AH/AL before next tile's convert
    }
}

// ==================== launch ====================
extern "C" void kernel_launch(void* const* d_in, const int* in_sizes, int n_in,
                              void* d_out, int out_size) {
    const float* x = (const float*)d_in[0];
    const float* w = (const float*)d_in[1];
    if (n_in >= 2 && in_sizes[0] < in_sizes[1]) {
        const float* tmp = x; x = w; w = tmp;
    }
    float* out = (float*)d_out;

    const int smemA = 128 * 129 * 4 + 128 * 4;  // 66560
    cudaFuncSetAttribute((const void*)buildq_kernel,
                         cudaFuncAttributeMaxDynamicSharedMemorySize, smemA);
    cudaFuncSetAttribute((const void*)mma_kernel,
                         cudaFuncAttributeMaxDynamicSharedMemorySize, SMEM_MMA);

    buildq_kernel<<<G * 8, 128, smemA>>>(w);
    mma_kernel<<<dim3(MROWS / (MT * TPC), G), 256, SMEM_MMA>>>(x, out);
}

// round 9
// speedup vs baseline: 1.2731x; 1.1827x over previous
#include <cuda_runtime.h>
#include <cuda_bf16.h>
#include <cstdint>

// out[g] = x[g] @ Q[g], Q = H_0..H_127 (Householder composition).
// Kernel A (buildq): build Q rows in parallel, emit Q^T (k-major) bf16 hi/lo.
// Kernel A2 (fragq): re-layout Q^T into per-lane mma B-fragment order
//                    (ldmatrix-equivalent), so the GEMM loads B with plain
//                    coalesced LDG.128 — no B smem, no B ldmatrix.
// Kernel B (mma):    bf16 mma.sync GEMM, 3-product hi/lo split, 32mx64n per
//                    warp, A-only smem (35 KB) -> 4 CTAs/SM = 16 warps/SM.

#define G 16
#define MROWS 16384
#define C 128
#define MT 64          // rows per CTA tile
#define SP 136         // padded smem row stride in bf16 elements

__device__ __nv_bfloat16 Qt_hi[G * C * C];   // [g][n][k], k contiguous
__device__ __nv_bfloat16 Qt_lo[G * C * C];
__device__ uint4 Qfrag_hi[G * 8 * 8 * 32];   // [g][jj][ks][lane], 512 KB
__device__ uint4 Qfrag_lo[G * 8 * 8 * 32];

__device__ __forceinline__ uint32_t smem_u32(const void* p) {
    uint32_t a;
    asm("{ .reg .u64 t; cvta.to.shared.u64 t, %1; cvt.u32.u64 %0, t; }"
        : "=r"(a) : "l"(p));
    return a;
}

__device__ __forceinline__ void ldmatrix_x4(uint32_t& r0, uint32_t& r1,
                                            uint32_t& r2, uint32_t& r3,
                                            uint32_t addr) {
    asm volatile("ldmatrix.sync.aligned.m8n8.x4.shared.b16 {%0,%1,%2,%3}, [%4];"
                 : "=r"(r0), "=r"(r1), "=r"(r2), "=r"(r3) : "r"(addr));
}

__device__ __forceinline__ void mma_bf16(float* d, const uint32_t* a,
                                         uint32_t b0, uint32_t b1) {
    asm volatile(
        "mma.sync.aligned.m16n8k16.row.col.f32.bf16.bf16.f32 "
        "{%0,%1,%2,%3}, {%4,%5,%6,%7}, {%8,%9}, {%0,%1,%2,%3};"
        : "+f"(d[0]), "+f"(d[1]), "+f"(d[2]), "+f"(d[3])
        : "r"(a[0]), "r"(a[1]), "r"(a[2]), "r"(a[3]), "r"(b0), "r"(b1));
}

// ==================== Kernel A: build Q (transposed, bf16 hi/lo) ====================
__global__ void __launch_bounds__(128) buildq_kernel(const float* __restrict__ W) {
    extern __shared__ float sm[];
    float* WshT = sm;              // [128][129]
    float* rden = sm + 128 * 129;  // [128]

    const int g  = blockIdx.x >> 3;
    const int rb = blockIdx.x & 7;
    const float* Wg = W + (size_t)g * C * C;
    const int t = threadIdx.x;

    #pragma unroll 8
    for (int k = 0; k < C; k++) WshT[t * 129 + k] = Wg[k * C + t];
    __syncthreads();

    {
        const float* row = &WshT[t * 129];
        float s = 0.0f;
        #pragma unroll 8
        for (int k = 0; k < C; k++) s = fmaf(row[k], row[k], s);
        rden[t] = 2.0f / s;
    }
    __syncthreads();

    const int r = t >> 3;
    const int p = t & 7;
    const int R = rb * 16 + r;

    float M[16];
    #pragma unroll
    for (int j = 0; j < 16; j++) M[j] = (R == (p + 8 * j)) ? 1.0f : 0.0f;

    for (int i = 0; i < C; i++) {
        const float* wrow = &WshT[i * 129 + p];
        float wv[16];
        float d0 = 0.0f, d1 = 0.0f;
        #pragma unroll
        for (int j = 0; j < 16; j++) {
            wv[j] = wrow[8 * j];
            if (j & 1) d1 = fmaf(M[j], wv[j], d1);
            else       d0 = fmaf(M[j], wv[j], d0);
        }
        float d = d0 + d1;
        d += __shfl_xor_sync(0xffffffffu, d, 1, 8);
        d += __shfl_xor_sync(0xffffffffu, d, 2, 8);
        d += __shfl_xor_sync(0xffffffffu, d, 4, 8);
        const float c = d * rden[i];
        #pragma unroll
        for (int j = 0; j < 16; j++) M[j] = fmaf(-c, wv[j], M[j]);
    }

    #pragma unroll
    for (int j = 0; j < 16; j++) {
        const int n = p + 8 * j;
        const size_t idx = ((size_t)g * C + n) * C + R;
        __nv_bfloat16 hi = __float2bfloat16_rn(M[j]);
        __nv_bfloat16 lo = __float2bfloat16_rn(M[j] - __bfloat162float(hi));
        Qt_hi[idx] = hi;
        Qt_lo[idx] = lo;
    }
}

// ==================== Kernel A2: Q^T -> mma B-fragment order ====================
// One block per group, 256 threads (8 warps). Warp w handles jj = w (16-col
// pair of n8 tiles), looping ks. Exactly reproduces the GEMM's previous
// ldmatrix addressing, then stores each lane's 4 regs contiguously.
#define FRAGQ_SMEM (2 * C * SP * 2)   // 69632

__global__ void __launch_bounds__(256) fragq_kernel() {
    extern __shared__ char smem[];
    const uint32_t sb = smem_u32(smem);
    const int g = blockIdx.x;
    const int t = threadIdx.x;
    const int w = t >> 5;
    const int l = t & 31;

    const uint4* qh = (const uint4*)(Qt_hi + (size_t)g * C * C);
    const uint4* ql = (const uint4*)(Qt_lo + (size_t)g * C * C);
    #pragma unroll
    for (int it = 0; it < 8; it++) {
        const int idx = t + 256 * it;          // 2048 uint4 per tensor
        const int row = idx >> 4;
        const int c8  = (idx & 15) * 8;
        const uint32_t off = (uint32_t)(row * SP + c8) * 2;
        *(uint4*)(smem + off) = qh[idx];
        *(uint4*)(smem + C * SP * 2 + off) = ql[idx];
    }
    __syncthreads();

    const int b_row_in = (l & 7) + 8 * (l >> 4);
    const int b_col8   = 8 * ((l >> 3) & 1);
    uint4* fh = Qfrag_hi + ((size_t)(g * 8 + w) * 8) * 32 + l;
    uint4* fl = Qfrag_lo + ((size_t)(g * 8 + w) * 8) * 32 + l;

    #pragma unroll
    for (int ks = 0; ks < 8; ks++) {
        const uint32_t boff =
            (uint32_t)((16 * w + b_row_in) * SP + 16 * ks + b_col8) * 2;
        uint4 vh, vl;
        ldmatrix_x4(vh.x, vh.y, vh.z, vh.w, sb + boff);
        ldmatrix_x4(vl.x, vl.y, vl.z, vl.w, sb + C * SP * 2 + boff);
        fh[ks * 32] = vh;
        fl[ks * 32] = vl;
    }
}

// ==================== Kernel B: mma.sync GEMM, B via LDG fragments ====================
#define AH_OFF 0
#define AL_OFF (MT * SP * 2)
#define SMEM_MMA (2 * MT * SP * 2)   // 34816 bytes

__global__ void __launch_bounds__(128, 4) mma_kernel(const float* __restrict__ X,
                                                     float* __restrict__ Out) {
    extern __shared__ char smem[];
    const uint32_t sb = smem_u32(smem);
    const int t  = threadIdx.x;
    const int w  = t >> 5;
    const int l  = t & 31;
    const int wm = w & 1;    // m-warp: rows [32*wm, 32*wm+32)
    const int wn = w >> 1;   // n-warp: cols [64*wn, 64*wn+64)  (jj = 4wn..4wn+3)
    const int m0 = blockIdx.x * MT;
    const int g  = blockIdx.y;

    // ---- stage x tile (64 x 128 fp32) -> bf16 hi/lo in smem ----
    const float4* xg = (const float4*)(X + ((size_t)g * MROWS + m0) * C);
    #pragma unroll
    for (int it = 0; it < 16; it++) {
        const int idx = t + 128 * it;          // 2048 float4
        const int row = idx >> 5;
        const int c4  = (idx & 31) * 4;
        const float4 v = xg[idx];
        const float vv[4] = {v.x, v.y, v.z, v.w};
        __nv_bfloat16 h[4], e[4];
        #pragma unroll
        for (int i = 0; i < 4; i++) {
            h[i] = __float2bfloat16_rn(vv[i]);
            e[i] = __float2bfloat16_rn(vv[i] - __bfloat162float(h[i]));
        }
        const uint32_t off = (uint32_t)(row * SP + c4) * 2;
        *(uint2*)(smem + AH_OFF + off) = *(const uint2*)h;
        *(uint2*)(smem + AL_OFF + off) = *(const uint2*)e;
    }
    __syncthreads();

    // ---- mainloop: per warp 32m x 64n ----
    float acc[2][8][4];
    #pragma unroll
    for (int mt = 0; mt < 2; mt++)
        #pragma unroll
        for (int nt = 0; nt < 8; nt++)
            #pragma unroll
            for (int i = 0; i < 4; i++) acc[mt][nt][i] = 0.0f;

    const int a_row  = (l & 7) + 8 * ((l >> 3) & 1);
    const int a_col8 = 8 * (l >> 4);
    const uint32_t aoff0 = (uint32_t)((32 * wm + a_row) * SP + a_col8) * 2;
    const uint32_t aoff1 = (uint32_t)((32 * wm + 16 + a_row) * SP + a_col8) * 2;

    // B fragment base: [g][jj][ks][lane]; jj = 4*wn + jjl
    const uint4* fh = Qfrag_hi + ((size_t)(g * 8 + 4 * wn) * 8) * 32 + l;
    const uint4* fl = Qfrag_lo + ((size_t)(g * 8 + 4 * wn) * 8) * 32 + l;

    #pragma unroll
    for (int ks = 0; ks < 8; ks++) {
        const int k0 = 16 * ks;
        uint32_t ah0[4], al0[4], ah1[4], al1[4];
        ldmatrix_x4(ah0[0], ah0[1], ah0[2], ah0[3], sb + AH_OFF + aoff0 + k0 * 2);
        ldmatrix_x4(al0[0], al0[1], al0[2], al0[3], sb + AL_OFF + aoff0 + k0 * 2);
        ldmatrix_x4(ah1[0], ah1[1], ah1[2], ah1[3], sb + AH_OFF + aoff1 + k0 * 2);
        ldmatrix_x4(al1[0], al1[1], al1[2], al1[3], sb + AL_OFF + aoff1 + k0 * 2);

        #pragma unroll
        for (int jjl = 0; jjl < 4; jjl++) {
            const uint4 bh = fh[(size_t)(jjl * 8 + ks) * 32];
            const uint4 bl = fl[(size_t)(jjl * 8 + ks) * 32];

            // n8 tile 2*jjl (cols 64wn+16jjl .. +8)
            mma_bf16(acc[0][2 * jjl],     ah0, bh.x, bh.y);
            mma_bf16(acc[0][2 * jjl],     ah0, bl.x, bl.y);
            mma_bf16(acc[0][2 * jjl],     al0, bh.x, bh.y);
            mma_bf16(acc[1][2 * jjl],     ah1, bh.x, bh.y);
            mma_bf16(acc[1][2 * jjl],     ah1, bl.x, bl.y);
            mma_bf16(acc[1][2 * jjl],     al1, bh.x, bh.y);
            // n8 tile 2*jjl+1 (cols +8 .. +16)
            mma_bf16(acc[0][2 * jjl + 1], ah0, bh.z, bh.w);
            mma_bf16(acc[0][2 * jjl + 1], ah0, bl.z, bl.w);
            mma_bf16(acc[0][2 * jjl + 1], al0, bh.z, bh.w);
            mma_bf16(acc[1][2 * jjl + 1], ah1, bh.z, bh.w);
            mma_bf16(acc[1][2 * jjl + 1], ah1, bl.z, bl.w);
            mma_bf16(acc[1][2 * jjl + 1], al1, bh.z, bh.w);
        }
    }

    // ---- epilogue ----
    const int rr = l >> 2;
    const int cn = 64 * wn + 2 * (l & 3);
    #pragma unroll
    for (int mt = 0; mt < 2; mt++) {
        const int r0 = 32 * wm + 16 * mt + rr;
        float* ob = Out + ((size_t)g * MROWS + m0 + r0) * C + cn;
        #pragma unroll
        for (int nt = 0; nt < 8; nt++) {
            *(float2*)(ob + 8 * nt)         = make_float2(acc[mt][nt][0], acc[mt][nt][1]);
            *(float2*)(ob + 8 * C + 8 * nt) = make_float2(acc[mt][nt][2], acc[mt][nt][3]);
        }
    }
}

// ==================== launch ====================
extern "C" void kernel_launch(void* const* d_in, const int* in_sizes, int n_in,
                              void* d_out, int out_size) {
    const float* x = (const float*)d_in[0];
    const float* w = (const float*)d_in[1];
    if (n_in >= 2 && in_sizes[0] < in_sizes[1]) {
        const float* tmp = x; x = w; w = tmp;
    }
    float* out = (float*)d_out;

    const int smemA = 128 * 129 * 4 + 128 * 4;  // 66560
    cudaFuncSetAttribute((const void*)buildq_kernel,
                         cudaFuncAttributeMaxDynamicSharedMemorySize, smemA);
    cudaFuncSetAttribute((const void*)fragq_kernel,
                         cudaFuncAttributeMaxDynamicSharedMemorySize, FRAGQ_SMEM);
    cudaFuncSetAttribute((const void*)mma_kernel,
                         cudaFuncAttributeMaxDynamicSharedMemorySize, SMEM_MMA);

    buildq_kernel<<<G * 8, 128, smemA>>>(w);
    fragq_kernel<<<G, 256, FRAGQ_SMEM>>>();
    mma_kernel<<<dim3(MROWS / MT, G), 128, SMEM_MMA>>>(x, out);
}